// round 16
// baseline (speedup 1.0000x reference)
#include <cuda_runtime.h>
#include <cuda_fp16.h>
#include <mma.h>
#include <cstddef>

using namespace nvcuda;

#define NN 100000
#define NE 3200000
#define NG 256
#define DIN 128
#define DH 64

// ---------------- scratch (device globals; no allocation) ----------------
__device__ int    g_degi[NN];          // src out-degree (side stream)
__device__ float  g_dinv[NN];
__device__ int    g_indeg[NN];
__device__ int    g_rowstart[NN];
__device__ int    g_fill[NN];
__device__ int    g_alloc;
__device__ int    g_csri[NE];          // src index only (weights factorized out)
__device__ int    g_batch[NN];
__device__ int    g_gstart[NG];
__device__ int    g_gend[NG];
__device__ int    g_flags[2];
__device__ float  g_wcat[DIN * 192];   // [W0-W2 | W1 | W2] for layer 1
// fp16 storage (uint2 = 4 halves; uint4-accessible)
__device__ uint2  g_P[(size_t)NN * 48];    // x @ wcat: P0|P1|P2
__device__ uint2  g_Rsc[(size_t)NN * 16];  // dinv*(P1 + 2*Lhat(P2))
__device__ uint2  g_h1[(size_t)NN * 16];
__device__ uint2  g_tb1[(size_t)NN * 16];
__device__ uint2  g_tb2[(size_t)NN * 16];
__device__ uint2  g_h2[(size_t)NN * 16];   // fp16 pool input
__device__ float  g_gsum[NG * DH];

// ---------------- fp16 helpers ----------------
__device__ __forceinline__ float4 ld_h4(const uint2* p) {
    uint2 u = *p;
    __half2 h0 = *reinterpret_cast<__half2*>(&u.x);
    __half2 h1 = *reinterpret_cast<__half2*>(&u.y);
    float2 f0 = __half22float2(h0), f1 = __half22float2(h1);
    return make_float4(f0.x, f0.y, f1.x, f1.y);
}
__device__ __forceinline__ uint2 st_h4(float4 v) {
    __half2 h0 = __floats2half2_rn(v.x, v.y);
    __half2 h1 = __floats2half2_rn(v.z, v.w);
    uint2 u;
    u.x = *reinterpret_cast<unsigned*>(&h0);
    u.y = *reinterpret_cast<unsigned*>(&h1);
    return u;
}
__device__ __forceinline__ void acc8(float4& a, float4& b, uint4 r, float w) {
    __half2* h = reinterpret_cast<__half2*>(&r);
    float2 f0 = __half22float2(h[0]), f1 = __half22float2(h[1]);
    float2 f2 = __half22float2(h[2]), f3 = __half22float2(h[3]);
    a.x += w * f0.x; a.y += w * f0.y; a.z += w * f1.x; a.w += w * f1.y;
    b.x += w * f2.x; b.y += w * f2.y; b.z += w * f3.x; b.w += w * f3.y;
}
__device__ __forceinline__ void unp8(float4& a, float4& b, uint4 r) {
    __half2* h = reinterpret_cast<__half2*>(&r);
    float2 f0 = __half22float2(h[0]), f1 = __half22float2(h[1]);
    float2 f2 = __half22float2(h[2]), f3 = __half22float2(h[3]);
    a = make_float4(f0.x, f0.y, f1.x, f1.y);
    b = make_float4(f2.x, f2.y, f3.x, f3.y);
}
__device__ __forceinline__ uint4 pk8(float4 a, float4 b) {
    uint2 lo = st_h4(a), hi = st_h4(b);
    return make_uint4(lo.x, lo.y, hi.x, hi.y);
}

// ---------------- init: zero scratch + dtype probe (block 0) ----------------
__global__ void k_init(const int* __restrict__ ei_raw, const int* __restrict__ batch_raw) {
    int i = blockIdx.x * blockDim.x + threadIdx.x;
    if (i < NN) { g_degi[i] = 0; g_indeg[i] = 0; g_fill[i] = 0; }
    if (i < NG * DH) g_gsum[i] = 0.f;
    if (i < NG) { g_gstart[i] = 0; g_gend[i] = 0; }
    if (i == 0) g_alloc = 0;
    if (blockIdx.x == 0) {
        __shared__ int s_ei, s_b;
        int t = threadIdx.x;
        if (t == 0) { s_ei = 0; s_b = 0; }
        __syncthreads();
        int acc_e = 0, acc_b = 0;
        for (int k = t; k < 4096; k += blockDim.x) acc_e |= ei_raw[2 * k + 1];
        for (int k = t; k < 4096; k += blockDim.x) acc_b |= batch_raw[2 * k + 1];
        atomicOr(&s_ei, acc_e);
        atomicOr(&s_b, acc_b);
        __syncthreads();
        if (t == 0) {
            g_flags[0] = (s_ei == 0) ? 1 : 0;
            g_flags[1] = (s_b == 0) ? 1 : 0;
        }
    }
}

// ---------------- main stream: in-degree only ----------------
__global__ void k_indeg(const void* __restrict__ ei_raw) {
    int t = blockIdx.x * blockDim.x + threadIdx.x;
    int e = t * 2;
    if (e >= NE) return;
    int d0, d1;
    if (g_flags[0]) {
        longlong2 dp = ((const longlong2*)((const long long*)ei_raw + NE))[t];
        d0 = (int)dp.x; d1 = (int)dp.y;
    } else {
        int2 dp = ((const int2*)((const int*)ei_raw + NE))[t];
        d0 = dp.x; d1 = dp.y;
    }
    d0 = min(max(d0, 0), NN - 1);
    d1 = min(max(d1, 0), NN - 1);
    atomicAdd(&g_indeg[d0], 1);
    atomicAdd(&g_indeg[d1], 1);
}

// side stream: src out-degree
__global__ void k_degsrc(const void* __restrict__ ei_raw) {
    int t = blockIdx.x * blockDim.x + threadIdx.x;
    int e = t * 2;
    if (e >= NE) return;
    int s0, s1;
    if (g_flags[0]) {
        longlong2 sp = ((const longlong2*)ei_raw)[t];
        s0 = (int)sp.x; s1 = (int)sp.y;
    } else {
        int2 sp = ((const int2*)ei_raw)[t];
        s0 = sp.x; s1 = sp.y;
    }
    s0 = min(max(s0, 0), NN - 1);
    s1 = min(max(s1, 0), NN - 1);
    atomicAdd(&g_degi[s0], 1);
    atomicAdd(&g_degi[s1], 1);
}

__global__ void k_dinv() {
    int i = blockIdx.x * blockDim.x + threadIdx.x;
    if (i < NN) {
        int d = g_degi[i];
        g_dinv[i] = (d > 0) ? rsqrtf((float)d) : 0.f;
    }
}

// CSR row allocation (warp-scan of indeg, one atomicAdd per warp)
__global__ void k_alloc() {
    int i = blockIdx.x * blockDim.x + threadIdx.x;
    int lane = threadIdx.x & 31;
    int v = (i < NN) ? g_indeg[i] : 0;
    int s = v;
#pragma unroll
    for (int o = 1; o < 32; o <<= 1) {
        int t = __shfl_up_sync(0xFFFFFFFF, s, o);
        if (lane >= o) s += t;
    }
    int total = __shfl_sync(0xFFFFFFFF, s, 31);
    int base = 0;
    if (lane == 31) base = atomicAdd(&g_alloc, total);
    base = __shfl_sync(0xFFFFFFFF, base, 31);
    if (i < NN) g_rowstart[i] = base + s - v;
}

// fill CSR (src only), 2 edges/thread
__global__ void k_fill(const void* __restrict__ ei_raw) {
    int t = blockIdx.x * blockDim.x + threadIdx.x;
    int e = t * 2;
    if (e >= NE) return;
    int s0, s1, d0, d1;
    if (g_flags[0]) {
        longlong2 sp = ((const longlong2*)ei_raw)[t];
        longlong2 dp = ((const longlong2*)((const long long*)ei_raw + NE))[t];
        s0 = (int)sp.x; s1 = (int)sp.y;
        d0 = (int)dp.x; d1 = (int)dp.y;
    } else {
        int2 sp = ((const int2*)ei_raw)[t];
        int2 dp = ((const int2*)((const int*)ei_raw + NE))[t];
        s0 = sp.x; s1 = sp.y;
        d0 = dp.x; d1 = dp.y;
    }
    s0 = min(max(s0, 0), NN - 1); s1 = min(max(s1, 0), NN - 1);
    d0 = min(max(d0, 0), NN - 1); d1 = min(max(d1, 0), NN - 1);
    int p0 = atomicAdd(&g_fill[d0], 1);
    g_csri[g_rowstart[d0] + p0] = s0;
    int p1 = atomicAdd(&g_fill[d1], 1);
    g_csri[g_rowstart[d1] + p1] = s1;
}

// ---------------- batch bookkeeping: decode + run boundaries (merged) ----------------
__global__ void k_batchb(const void* __restrict__ batch_raw) {
    int i = blockIdx.x * blockDim.x + threadIdx.x;
    if (i >= NN) return;
    int b, bp = -1, bn = -1;
    if (g_flags[1]) {
        const long long* p = (const long long*)batch_raw;
        b = (int)p[i];
        if (i > 0) bp = (int)p[i - 1];
        if (i < NN - 1) bn = (int)p[i + 1];
    } else {
        const int* p = (const int*)batch_raw;
        b = p[i];
        if (i > 0) bp = p[i - 1];
        if (i < NN - 1) bn = p[i + 1];
    }
    b = min(max(b, 0), NG - 1);
    if (i > 0) bp = min(max(bp, 0), NG - 1);
    if (i < NN - 1) bn = min(max(bn, 0), NG - 1);
    g_batch[i] = b;
    if (i == 0 || bp != b) g_gstart[b] = i;
    if (i == NN - 1 || bn != b) g_gend[b] = i + 1;
}

// build Wcat = [W0-W2 | W1 | W2] (128 x 192)
__global__ void k_wcat(const float* __restrict__ W1) {
    int t = blockIdx.x * blockDim.x + threadIdx.x;
    if (t >= DIN * 192) return;
    int i = t / 192, o = t % 192;
    float v;
    if (o < 64)       v = W1[i * 64 + o] - W1[2 * 8192 + i * 64 + o];
    else if (o < 128) v = W1[8192 + i * 64 + (o - 64)];
    else              v = W1[2 * 8192 + i * 64 + (o - 128)];
    g_wcat[t] = v;
}

// ---------------- tensor-core GEMM 1: P = x @ Wcat ----------------
__global__ void k_gemm_p(const float4* __restrict__ A4) {
    __shared__ __align__(32) __half sA[128 * 40];
    __shared__ __align__(32) __half sB[32 * 72];
    __shared__ __align__(32) float  sC[128 * 64];
    const int tid = threadIdx.x;
    const int m0 = blockIdx.x * 128;
    const int n0 = blockIdx.y * 64;
    const int wid = tid >> 5;
    const int wm = wid & 3, wn = wid >> 2;

    wmma::fragment<wmma::accumulator, 16, 16, 16, float> c[2][2];
#pragma unroll
    for (int i = 0; i < 2; i++)
#pragma unroll
        for (int j = 0; j < 2; j++) wmma::fill_fragment(c[i][j], 0.f);

    const int arow = tid >> 1, aseg = tid & 1;
    const int brow = tid >> 3, bc8 = (tid & 7) * 8;

    for (int k0 = 0; k0 < 128; k0 += 32) {
        __syncthreads();
        {
            int gm = m0 + arow;
            uint2* dst = reinterpret_cast<uint2*>(sA) + arow * 10 + aseg * 4;
            if (gm < NN) {
                const float4* src = A4 + (size_t)gm * 32 + (k0 >> 2) + aseg * 4;
#pragma unroll
                for (int q = 0; q < 4; q++) dst[q] = st_h4(src[q]);
            } else {
                uint2 z = make_uint2(0u, 0u);
#pragma unroll
                for (int q = 0; q < 4; q++) dst[q] = z;
            }
        }
        {
            const float4* src = (const float4*)(g_wcat + (size_t)(k0 + brow) * 192 + n0 + bc8);
            uint2* dst = reinterpret_cast<uint2*>(sB) + brow * 18 + (tid & 7) * 2;
            dst[0] = st_h4(src[0]);
            dst[1] = st_h4(src[1]);
        }
        __syncthreads();
#pragma unroll
        for (int kk = 0; kk < 32; kk += 16) {
            wmma::fragment<wmma::matrix_a, 16, 16, 16, __half, wmma::row_major> a[2];
            wmma::fragment<wmma::matrix_b, 16, 16, 16, __half, wmma::row_major> b[2];
#pragma unroll
            for (int i = 0; i < 2; i++)
                wmma::load_matrix_sync(a[i], sA + (wm * 32 + i * 16) * 40 + kk, 40);
#pragma unroll
            for (int j = 0; j < 2; j++)
                wmma::load_matrix_sync(b[j], sB + kk * 72 + wn * 32 + j * 16, 72);
#pragma unroll
            for (int i = 0; i < 2; i++)
#pragma unroll
                for (int j = 0; j < 2; j++) wmma::mma_sync(c[i][j], a[i], b[j], c[i][j]);
        }
    }
#pragma unroll
    for (int i = 0; i < 2; i++)
#pragma unroll
        for (int j = 0; j < 2; j++)
            wmma::store_matrix_sync(sC + (wm * 32 + i * 16) * 64 + wn * 32 + j * 16,
                                    c[i][j], 64, wmma::mem_row_major);
    __syncthreads();
    {
        int row = tid >> 1, seg = tid & 1;
        int gm = m0 + row;
        if (gm < NN) {
            const float* src = sC + row * 64 + seg * 32;
            uint2* dst = g_P + (size_t)gm * 48 + (n0 >> 2) + seg * 8;
#pragma unroll
            for (int q = 0; q < 8; q++)
                dst[q] = st_h4(make_float4(src[q * 4], src[q * 4 + 1], src[q * 4 + 2], src[q * 4 + 3]));
        }
    }
}

// ---------------- gathers: 8 lanes/node, uint4 loads, 4-edge unroll (R13 form) ----------------
// gather 1: sum2 = sum dinv[s]*P2[s]; Rsc = dv*P1 - 2*dv^2*sum2
__global__ void k_gatherS() {
    int g = blockIdx.x * blockDim.x + threadIdx.x;
    int node = g >> 3;
    if (node >= NN) return;
    int lane = g & 7;
    int start = g_rowstart[node];
    int cnt = g_indeg[node];
    float4 sa = make_float4(0.f, 0.f, 0.f, 0.f);
    float4 sb = make_float4(0.f, 0.f, 0.f, 0.f);
    const int* cs = g_csri + start;
    int j = 0;
    for (; j + 4 <= cnt; j += 4) {
        int e[4];
        float ds[4];
        uint4 r[4];
#pragma unroll
        for (int u = 0; u < 4; u++) e[u] = cs[j + u];
#pragma unroll
        for (int u = 0; u < 4; u++) {
            ds[u] = g_dinv[e[u]];
            r[u] = *(const uint4*)(g_P + (size_t)e[u] * 48 + 32 + lane * 2);
        }
#pragma unroll
        for (int u = 0; u < 4; u++) acc8(sa, sb, r[u], ds[u]);
    }
    for (; j < cnt; j++) {
        int e0 = cs[j];
        uint4 r0 = *(const uint4*)(g_P + (size_t)e0 * 48 + 32 + lane * 2);
        acc8(sa, sb, r0, g_dinv[e0]);
    }
    float dv = g_dinv[node];
    float m = -2.f * dv * dv;
    float4 pa, pb;
    unp8(pa, pb, *(const uint4*)(g_P + (size_t)node * 48 + 16 + lane * 2));
    float4 oa = make_float4(dv * pa.x + m * sa.x, dv * pa.y + m * sa.y,
                            dv * pa.z + m * sa.z, dv * pa.w + m * sa.w);
    float4 ob = make_float4(dv * pb.x + m * sb.x, dv * pb.y + m * sb.y,
                            dv * pb.z + m * sb.z, dv * pb.w + m * sb.w);
    *(uint4*)(g_Rsc + (size_t)node * 16 + lane * 2) = pk8(oa, ob);
}

// gather 2: h1 = relu(P0 + b - dv*sum(Rsc[s]))   (Rsc already carries dinv)
__global__ void k_combine64(const float* __restrict__ b1) {
    int g = blockIdx.x * blockDim.x + threadIdx.x;
    int node = g >> 3;
    if (node >= NN) return;
    int lane = g & 7;
    int start = g_rowstart[node];
    int cnt = g_indeg[node];
    float4 sa = make_float4(0.f, 0.f, 0.f, 0.f);
    float4 sb = make_float4(0.f, 0.f, 0.f, 0.f);
    const int* cs = g_csri + start;
    int j = 0;
    for (; j + 4 <= cnt; j += 4) {
        int e[4];
        uint4 r[4];
#pragma unroll
        for (int u = 0; u < 4; u++) e[u] = cs[j + u];
#pragma unroll
        for (int u = 0; u < 4; u++) r[u] = *(const uint4*)(g_Rsc + (size_t)e[u] * 16 + lane * 2);
#pragma unroll
        for (int u = 0; u < 4; u++) acc8(sa, sb, r[u], 1.f);
    }
    for (; j < cnt; j++) {
        acc8(sa, sb, *(const uint4*)(g_Rsc + (size_t)cs[j] * 16 + lane * 2), 1.f);
    }
    float dv = g_dinv[node];
    float4 pa, pb;
    unp8(pa, pb, *(const uint4*)(g_P + (size_t)node * 48 + lane * 2));
    float4 ba = *(const float4*)(b1 + lane * 8);
    float4 bb = *(const float4*)(b1 + lane * 8 + 4);
    float4 oa, ob;
    oa.x = fmaxf(pa.x + ba.x - dv * sa.x, 0.f);
    oa.y = fmaxf(pa.y + ba.y - dv * sa.y, 0.f);
    oa.z = fmaxf(pa.z + ba.z - dv * sa.z, 0.f);
    oa.w = fmaxf(pa.w + ba.w - dv * sa.w, 0.f);
    ob.x = fmaxf(pb.x + bb.x - dv * sb.x, 0.f);
    ob.y = fmaxf(pb.y + bb.y - dv * sb.y, 0.f);
    ob.z = fmaxf(pb.z + bb.z - dv * sb.z, 0.f);
    ob.w = fmaxf(pb.w + bb.w - dv * sb.w, 0.f);
    *(uint4*)(g_h1 + (size_t)node * 16 + lane * 2) = pk8(oa, ob);
}

// generic D=64 factorized gather with PER-EDGE dinv (no scaled copies):
// val = mul*dv*sum(dinv[s]*in[s]) - (subsrc? subsrc[node]:0)
__global__ void k_gather64(const uint2* __restrict__ in, uint2* __restrict__ out,
                           const uint2* __restrict__ subsrc, float mul) {
    int g = blockIdx.x * blockDim.x + threadIdx.x;
    int node = g >> 3;
    if (node >= NN) return;
    int lane = g & 7;
    int start = g_rowstart[node];
    int cnt = g_indeg[node];
    float4 sa = make_float4(0.f, 0.f, 0.f, 0.f);
    float4 sb = make_float4(0.f, 0.f, 0.f, 0.f);
    const int* cs = g_csri + start;
    int j = 0;
    for (; j + 4 <= cnt; j += 4) {
        int e[4];
        float ds[4];
        uint4 r[4];
#pragma unroll
        for (int u = 0; u < 4; u++) e[u] = cs[j + u];
#pragma unroll
        for (int u = 0; u < 4; u++) {
            ds[u] = g_dinv[e[u]];
            r[u] = *(const uint4*)(in + (size_t)e[u] * 16 + lane * 2);
        }
#pragma unroll
        for (int u = 0; u < 4; u++) acc8(sa, sb, r[u], ds[u]);
    }
    for (; j < cnt; j++) {
        int e0 = cs[j];
        acc8(sa, sb, *(const uint4*)(in + (size_t)e0 * 16 + lane * 2), g_dinv[e0]);
    }
    float dv = g_dinv[node];
    float m = mul * dv;
    float4 va = make_float4(m * sa.x, m * sa.y, m * sa.z, m * sa.w);
    float4 vb = make_float4(m * sb.x, m * sb.y, m * sb.z, m * sb.w);
    if (subsrc) {
        float4 ta, tb;
        unp8(ta, tb, *(const uint4*)(subsrc + (size_t)node * 16 + lane * 2));
        va.x -= ta.x; va.y -= ta.y; va.z -= ta.z; va.w -= ta.w;
        vb.x -= tb.x; vb.y -= tb.y; vb.z -= tb.z; vb.w -= tb.w;
    }
    *(uint4*)(out + (size_t)node * 16 + lane * 2) = pk8(va, vb);
}

// ---------------- tensor-core GEMM 2: h2 = relu([h1|tb1|tb2] @ W2 + b2), fp16 out ----------------
__global__ void k_gemm3(const float* __restrict__ W, const float* __restrict__ bias) {
    __shared__ __align__(32) __half sA[128 * 40];
    __shared__ __align__(32) __half sB[32 * 72];
    __shared__ __align__(32) float  sC[128 * 64];
    const int tid = threadIdx.x;
    const int m0 = blockIdx.x * 128;
    const int wid = tid >> 5;
    const int wm = wid & 3, wn = wid >> 2;

    wmma::fragment<wmma::accumulator, 16, 16, 16, float> c[2][2];
#pragma unroll
    for (int i = 0; i < 2; i++)
#pragma unroll
        for (int j = 0; j < 2; j++) wmma::fill_fragment(c[i][j], 0.f);

    const int arow = tid >> 1, aseg = tid & 1;
    const int brow = tid >> 3, bc8 = (tid & 7) * 8;

    for (int k0 = 0; k0 < 192; k0 += 32) {
        const uint2* Asrc = (k0 < 64) ? g_h1 : (k0 < 128 ? g_tb1 : g_tb2);
        const int koff = (k0 & 63) >> 2;
        __syncthreads();
        {
            int gm = m0 + arow;
            uint2* dst = reinterpret_cast<uint2*>(sA) + arow * 10 + aseg * 4;
            if (gm < NN) {
                const uint2* src = Asrc + (size_t)gm * 16 + koff + aseg * 4;
#pragma unroll
                for (int q = 0; q < 4; q++) dst[q] = src[q];
            } else {
                uint2 z = make_uint2(0u, 0u);
#pragma unroll
                for (int q = 0; q < 4; q++) dst[q] = z;
            }
        }
        {
            const float4* src = (const float4*)(W + (size_t)(k0 + brow) * 64 + bc8);
            uint2* dst = reinterpret_cast<uint2*>(sB) + brow * 18 + (tid & 7) * 2;
            dst[0] = st_h4(src[0]);
            dst[1] = st_h4(src[1]);
        }
        __syncthreads();
#pragma unroll
        for (int kk = 0; kk < 32; kk += 16) {
            wmma::fragment<wmma::matrix_a, 16, 16, 16, __half, wmma::row_major> a[2];
            wmma::fragment<wmma::matrix_b, 16, 16, 16, __half, wmma::row_major> b[2];
#pragma unroll
            for (int i = 0; i < 2; i++)
                wmma::load_matrix_sync(a[i], sA + (wm * 32 + i * 16) * 40 + kk, 40);
#pragma unroll
            for (int j = 0; j < 2; j++)
                wmma::load_matrix_sync(b[j], sB + kk * 72 + wn * 32 + j * 16, 72);
#pragma unroll
            for (int i = 0; i < 2; i++)
#pragma unroll
                for (int j = 0; j < 2; j++) wmma::mma_sync(c[i][j], a[i], b[j], c[i][j]);
        }
    }
#pragma unroll
    for (int i = 0; i < 2; i++)
#pragma unroll
        for (int j = 0; j < 2; j++)
            wmma::store_matrix_sync(sC + (wm * 32 + i * 16) * 64 + wn * 32 + j * 16,
                                    c[i][j], 64, wmma::mem_row_major);
    __syncthreads();
    {
        int row = tid >> 1, seg = tid & 1;
        int gm = m0 + row;
        if (gm < NN) {
            const float* src = sC + row * 64 + seg * 32;
#pragma unroll
            for (int q = 0; q < 8; q++) {
                float4 bb = *(const float4*)(bias + seg * 32 + q * 4);
                float4 o;
                o.x = fmaxf(src[q * 4 + 0] + bb.x, 0.f);
                o.y = fmaxf(src[q * 4 + 1] + bb.y, 0.f);
                o.z = fmaxf(src[q * 4 + 2] + bb.z, 0.f);
                o.w = fmaxf(src[q * 4 + 3] + bb.w, 0.f);
                g_h2[(size_t)gm * 16 + seg * 8 + q] = st_h4(o);
            }
        }
    }
}

// ---------------- pooling + FC ----------------
__global__ void k_pool() {
    int col4 = threadIdx.x & 15;
    int sub = threadIdx.x >> 4;
    int n0 = blockIdx.x * 512 + sub * 32;
    float4 acc = make_float4(0.f, 0.f, 0.f, 0.f);
    int cur = -1;
    for (int k = 0; k < 32; k++) {
        int n = n0 + k;
        if (n >= NN) break;
        int gph = g_batch[n];
        if (gph != cur) {
            if (cur >= 0) {
                atomicAdd(&g_gsum[cur * 64 + col4 * 4 + 0], acc.x);
                atomicAdd(&g_gsum[cur * 64 + col4 * 4 + 1], acc.y);
                atomicAdd(&g_gsum[cur * 64 + col4 * 4 + 2], acc.z);
                atomicAdd(&g_gsum[cur * 64 + col4 * 4 + 3], acc.w);
            }
            cur = gph;
            acc = make_float4(0.f, 0.f, 0.f, 0.f);
        }
        float4 v = ld_h4(g_h2 + (size_t)n * 16 + col4);
        acc.x += v.x; acc.y += v.y; acc.z += v.z; acc.w += v.w;
    }
    if (cur >= 0) {
        atomicAdd(&g_gsum[cur * 64 + col4 * 4 + 0], acc.x);
        atomicAdd(&g_gsum[cur * 64 + col4 * 4 + 1], acc.y);
        atomicAdd(&g_gsum[cur * 64 + col4 * 4 + 2], acc.z);
        atomicAdd(&g_gsum[cur * 64 + col4 * 4 + 3], acc.w);
    }
}

__global__ void k_final(const float* __restrict__ Wfc, const float* __restrict__ bfc,
                        float* __restrict__ out) {
    int gph = threadIdx.x;
    if (gph < NG) {
        float c = fmaxf((float)(g_gend[gph] - g_gstart[gph]), 1.0f);
        float s = 0.f;
#pragma unroll
        for (int o = 0; o < 64; o++) s += g_gsum[gph * 64 + o] * Wfc[o];
        out[gph] = s / c + bfc[0];
    }
}

// ---------------- launch ----------------
extern "C" void kernel_launch(void* const* d_in, const int* in_sizes, int n_in,
                              void* d_out, int out_size) {
    const float *x = nullptr, *W1 = nullptr, *b1 = nullptr, *W2 = nullptr,
                *b2 = nullptr, *Wfc = nullptr, *bfc = nullptr;
    const void *ei = nullptr, *batch = nullptr;
    int idx64[3] = {-1, -1, -1};
    int n64 = 0, idxW2 = -1;
    for (int i = 0; i < n_in; i++) {
        int s = in_sizes[i];
        switch (s) {
            case 12800000: x = (const float*)d_in[i]; break;
            case 6400000:  ei = d_in[i]; break;
            case 100000:   batch = d_in[i]; break;
            case 24576:    W1 = (const float*)d_in[i]; break;
            case 12288:    W2 = (const float*)d_in[i]; idxW2 = i; break;
            case 1:        bfc = (const float*)d_in[i]; break;
            case 64:       if (n64 < 3) idx64[n64++] = i; break;
            default: break;
        }
    }
    if (n64 == 3) {
        if (idx64[0] < idxW2) {
            b1 = (const float*)d_in[idx64[0]];
            b2 = (const float*)d_in[idx64[1]];
            Wfc = (const float*)d_in[idx64[2]];
        } else {
            Wfc = (const float*)d_in[idx64[0]];
            b1 = (const float*)d_in[idx64[1]];
            b2 = (const float*)d_in[idx64[2]];
        }
    }
    float* out = (float*)d_out;

    uint2 *h1, *tb1, *tb2;
    cudaGetSymbolAddress((void**)&h1, g_h1);
    cudaGetSymbolAddress((void**)&tb1, g_tb1);
    cudaGetSymbolAddress((void**)&tb2, g_tb2);

    static cudaStream_t s_side = nullptr;
    static cudaEvent_t s_fork = nullptr, s_join = nullptr;
    if (!s_side) {
        cudaStreamCreateWithFlags(&s_side, cudaStreamNonBlocking);
        cudaEventCreateWithFlags(&s_fork, cudaEventDisableTiming);
        cudaEventCreateWithFlags(&s_join, cudaEventDisableTiming);
    }

    const int TB = 256;
    const int g8 = (NN * 8 + TB - 1) / TB;

    // init (zero + dtype probe) FIRST, then fork
    k_init<<<(NN + TB - 1) / TB, TB>>>((const int*)ei, (const int*)batch);
    cudaEventRecord(s_fork, 0);
    cudaStreamWaitEvent(s_side, s_fork, 0);

    // side stream: weight prep + layer-1 GEMM + src-degree/dinv
    {
        dim3 gp((NN + 127) / 128, 3);
        k_wcat<<<(DIN * 192 + TB - 1) / TB, TB, 0, s_side>>>(W1);
        k_gemm_p<<<gp, TB, 0, s_side>>>((const float4*)x);
        k_degsrc<<<(NE / 2 + TB - 1) / TB, TB, 0, s_side>>>(ei);
        k_dinv<<<(NN + TB - 1) / TB, TB, 0, s_side>>>();
        cudaEventRecord(s_join, s_side);
    }

    // main stream: CSR build (in-degree only) + batch bookkeeping
    k_indeg<<<(NE / 2 + TB - 1) / TB, TB>>>(ei);
    k_batchb<<<(NN + TB - 1) / TB, TB>>>(batch);
    k_alloc<<<(NN + TB - 1) / TB, TB>>>();
    k_fill<<<(NE / 2 + TB - 1) / TB, TB>>>(ei);

    cudaStreamWaitEvent(0, s_join, 0);

    // layer 1: Rsc = dinv*(P1 + 2*Lhat(P2)); h1 = relu(P0 + b1 - dv*sum Rsc)
    k_gatherS<<<g8, TB>>>();
    k_combine64<<<g8, TB>>>(b1);

    // layer 2: tb1 = Lhat(h1); tb2 = 2*Lhat(tb1) - h1; h2 = relu([h1|tb1|tb2]@W2 + b2)
    k_gather64<<<g8, TB>>>(h1, tb1, nullptr, -1.0f);
    k_gather64<<<g8, TB>>>(tb1, tb2, h1, -2.0f);
    k_gemm3<<<(NN + 127) / 128, TB>>>(W2, b2);

    // mean pool per graph + FC
    k_pool<<<(NN + 511) / 512, TB>>>();
    k_final<<<1, TB>>>(Wfc, bfc, out);
}

// round 17
// speedup vs baseline: 1.4935x; 1.4935x over previous
#include <cuda_runtime.h>
#include <cuda_fp16.h>
#include <mma.h>
#include <cstddef>

using namespace nvcuda;

#define NN 100000
#define NE 3200000
#define NG 256
#define DIN 128
#define DH 64

// ---------------- scratch (device globals; no allocation) ----------------
__device__ int    g_degi[NN];          // src out-degree (side stream)
__device__ float  g_dinv[NN];
__device__ int    g_indeg[NN];
__device__ int    g_rowstart[NN];
__device__ int    g_fill[NN];
__device__ int    g_alloc;
__device__ int    g_csri[NE];          // src index only (weights factorized out)
__device__ int    g_batch[NN];
__device__ int    g_gstart[NG];
__device__ int    g_gend[NG];
__device__ int    g_flags[2];
__device__ float  g_wcat[DIN * 192];   // [W0-W2 | W1 | W2] for layer 1
// fp16 storage (uint2 = 4 halves; uint4-accessible)
__device__ uint2  g_P[(size_t)NN * 48];    // x @ wcat: P0|P1|P2
__device__ uint2  g_Rsc[(size_t)NN * 16];  // dinv*(P1 + 2*Lhat(P2))
__device__ uint2  g_h1[(size_t)NN * 16];
__device__ uint2  g_h1s[(size_t)NN * 16];  // dinv * h1
__device__ uint2  g_tb1[(size_t)NN * 16];
__device__ uint2  g_tb1s[(size_t)NN * 16];
__device__ uint2  g_tb2[(size_t)NN * 16];
__device__ uint2  g_h2[(size_t)NN * 16];   // fp16 pool input
__device__ float  g_gsum[NG * DH];

// ---------------- fp16 helpers ----------------
__device__ __forceinline__ float4 ld_h4(const uint2* p) {
    uint2 u = *p;
    __half2 h0 = *reinterpret_cast<__half2*>(&u.x);
    __half2 h1 = *reinterpret_cast<__half2*>(&u.y);
    float2 f0 = __half22float2(h0), f1 = __half22float2(h1);
    return make_float4(f0.x, f0.y, f1.x, f1.y);
}
__device__ __forceinline__ uint2 st_h4(float4 v) {
    __half2 h0 = __floats2half2_rn(v.x, v.y);
    __half2 h1 = __floats2half2_rn(v.z, v.w);
    uint2 u;
    u.x = *reinterpret_cast<unsigned*>(&h0);
    u.y = *reinterpret_cast<unsigned*>(&h1);
    return u;
}
__device__ __forceinline__ void acc8(float4& a, float4& b, uint4 r, float w) {
    __half2* h = reinterpret_cast<__half2*>(&r);
    float2 f0 = __half22float2(h[0]), f1 = __half22float2(h[1]);
    float2 f2 = __half22float2(h[2]), f3 = __half22float2(h[3]);
    a.x += w * f0.x; a.y += w * f0.y; a.z += w * f1.x; a.w += w * f1.y;
    b.x += w * f2.x; b.y += w * f2.y; b.z += w * f3.x; b.w += w * f3.y;
}
__device__ __forceinline__ void unp8(float4& a, float4& b, uint4 r) {
    __half2* h = reinterpret_cast<__half2*>(&r);
    float2 f0 = __half22float2(h[0]), f1 = __half22float2(h[1]);
    float2 f2 = __half22float2(h[2]), f3 = __half22float2(h[3]);
    a = make_float4(f0.x, f0.y, f1.x, f1.y);
    b = make_float4(f2.x, f2.y, f3.x, f3.y);
}
__device__ __forceinline__ uint4 pk8(float4 a, float4 b) {
    uint2 lo = st_h4(a), hi = st_h4(b);
    return make_uint4(lo.x, lo.y, hi.x, hi.y);
}

// ---------------- init: zero scratch + dtype probe (block 0) ----------------
__global__ void k_init(const int* __restrict__ ei_raw, const int* __restrict__ batch_raw) {
    int i = blockIdx.x * blockDim.x + threadIdx.x;
    if (i < NN) { g_degi[i] = 0; g_indeg[i] = 0; g_fill[i] = 0; }
    if (i < NG * DH) g_gsum[i] = 0.f;
    if (i < NG) { g_gstart[i] = 0; g_gend[i] = 0; }
    if (i == 0) g_alloc = 0;
    if (blockIdx.x == 0) {
        __shared__ int s_ei, s_b;
        int t = threadIdx.x;
        if (t == 0) { s_ei = 0; s_b = 0; }
        __syncthreads();
        int acc_e = 0, acc_b = 0;
        for (int k = t; k < 4096; k += blockDim.x) acc_e |= ei_raw[2 * k + 1];
        for (int k = t; k < 4096; k += blockDim.x) acc_b |= batch_raw[2 * k + 1];
        atomicOr(&s_ei, acc_e);
        atomicOr(&s_b, acc_b);
        __syncthreads();
        if (t == 0) {
            g_flags[0] = (s_ei == 0) ? 1 : 0;
            g_flags[1] = (s_b == 0) ? 1 : 0;
        }
    }
}

// ---------------- main stream: in-degree only ----------------
__global__ void k_indeg(const void* __restrict__ ei_raw) {
    int t = blockIdx.x * blockDim.x + threadIdx.x;
    int e = t * 2;
    if (e >= NE) return;
    int d0, d1;
    if (g_flags[0]) {
        longlong2 dp = ((const longlong2*)((const long long*)ei_raw + NE))[t];
        d0 = (int)dp.x; d1 = (int)dp.y;
    } else {
        int2 dp = ((const int2*)((const int*)ei_raw + NE))[t];
        d0 = dp.x; d1 = dp.y;
    }
    d0 = min(max(d0, 0), NN - 1);
    d1 = min(max(d1, 0), NN - 1);
    atomicAdd(&g_indeg[d0], 1);
    atomicAdd(&g_indeg[d1], 1);
}

// side stream: src out-degree
__global__ void k_degsrc(const void* __restrict__ ei_raw) {
    int t = blockIdx.x * blockDim.x + threadIdx.x;
    int e = t * 2;
    if (e >= NE) return;
    int s0, s1;
    if (g_flags[0]) {
        longlong2 sp = ((const longlong2*)ei_raw)[t];
        s0 = (int)sp.x; s1 = (int)sp.y;
    } else {
        int2 sp = ((const int2*)ei_raw)[t];
        s0 = sp.x; s1 = sp.y;
    }
    s0 = min(max(s0, 0), NN - 1);
    s1 = min(max(s1, 0), NN - 1);
    atomicAdd(&g_degi[s0], 1);
    atomicAdd(&g_degi[s1], 1);
}

__global__ void k_dinv() {
    int i = blockIdx.x * blockDim.x + threadIdx.x;
    if (i < NN) {
        int d = g_degi[i];
        g_dinv[i] = (d > 0) ? rsqrtf((float)d) : 0.f;
    }
}

// CSR row allocation (warp-scan of indeg, one atomicAdd per warp)
__global__ void k_alloc() {
    int i = blockIdx.x * blockDim.x + threadIdx.x;
    int lane = threadIdx.x & 31;
    int v = (i < NN) ? g_indeg[i] : 0;
    int s = v;
#pragma unroll
    for (int o = 1; o < 32; o <<= 1) {
        int t = __shfl_up_sync(0xFFFFFFFF, s, o);
        if (lane >= o) s += t;
    }
    int total = __shfl_sync(0xFFFFFFFF, s, 31);
    int base = 0;
    if (lane == 31) base = atomicAdd(&g_alloc, total);
    base = __shfl_sync(0xFFFFFFFF, base, 31);
    if (i < NN) g_rowstart[i] = base + s - v;
}

// fill CSR (src only), 2 edges/thread
__global__ void k_fill(const void* __restrict__ ei_raw) {
    int t = blockIdx.x * blockDim.x + threadIdx.x;
    int e = t * 2;
    if (e >= NE) return;
    int s0, s1, d0, d1;
    if (g_flags[0]) {
        longlong2 sp = ((const longlong2*)ei_raw)[t];
        longlong2 dp = ((const longlong2*)((const long long*)ei_raw + NE))[t];
        s0 = (int)sp.x; s1 = (int)sp.y;
        d0 = (int)dp.x; d1 = (int)dp.y;
    } else {
        int2 sp = ((const int2*)ei_raw)[t];
        int2 dp = ((const int2*)((const int*)ei_raw + NE))[t];
        s0 = sp.x; s1 = sp.y;
        d0 = dp.x; d1 = dp.y;
    }
    s0 = min(max(s0, 0), NN - 1); s1 = min(max(s1, 0), NN - 1);
    d0 = min(max(d0, 0), NN - 1); d1 = min(max(d1, 0), NN - 1);
    int p0 = atomicAdd(&g_fill[d0], 1);
    g_csri[g_rowstart[d0] + p0] = s0;
    int p1 = atomicAdd(&g_fill[d1], 1);
    g_csri[g_rowstart[d1] + p1] = s1;
}

// ---------------- batch bookkeeping: decode + run boundaries (merged) ----------------
__global__ void k_batchb(const void* __restrict__ batch_raw) {
    int i = blockIdx.x * blockDim.x + threadIdx.x;
    if (i >= NN) return;
    int b, bp = -1, bn = -1;
    if (g_flags[1]) {
        const long long* p = (const long long*)batch_raw;
        b = (int)p[i];
        if (i > 0) bp = (int)p[i - 1];
        if (i < NN - 1) bn = (int)p[i + 1];
    } else {
        const int* p = (const int*)batch_raw;
        b = p[i];
        if (i > 0) bp = p[i - 1];
        if (i < NN - 1) bn = p[i + 1];
    }
    b = min(max(b, 0), NG - 1);
    if (i > 0) bp = min(max(bp, 0), NG - 1);
    if (i < NN - 1) bn = min(max(bn, 0), NG - 1);
    g_batch[i] = b;
    if (i == 0 || bp != b) g_gstart[b] = i;
    if (i == NN - 1 || bn != b) g_gend[b] = i + 1;
}

// build Wcat = [W0-W2 | W1 | W2] (128 x 192)
__global__ void k_wcat(const float* __restrict__ W1) {
    int t = blockIdx.x * blockDim.x + threadIdx.x;
    if (t >= DIN * 192) return;
    int i = t / 192, o = t % 192;
    float v;
    if (o < 64)       v = W1[i * 64 + o] - W1[2 * 8192 + i * 64 + o];
    else if (o < 128) v = W1[8192 + i * 64 + (o - 64)];
    else              v = W1[2 * 8192 + i * 64 + (o - 128)];
    g_wcat[t] = v;
}

// ---------------- tensor-core GEMM 1: P = x @ Wcat ----------------
__global__ void k_gemm_p(const float4* __restrict__ A4) {
    __shared__ __align__(32) __half sA[128 * 40];
    __shared__ __align__(32) __half sB[32 * 72];
    __shared__ __align__(32) float  sC[128 * 64];
    const int tid = threadIdx.x;
    const int m0 = blockIdx.x * 128;
    const int n0 = blockIdx.y * 64;
    const int wid = tid >> 5;
    const int wm = wid & 3, wn = wid >> 2;

    wmma::fragment<wmma::accumulator, 16, 16, 16, float> c[2][2];
#pragma unroll
    for (int i = 0; i < 2; i++)
#pragma unroll
        for (int j = 0; j < 2; j++) wmma::fill_fragment(c[i][j], 0.f);

    const int arow = tid >> 1, aseg = tid & 1;
    const int brow = tid >> 3, bc8 = (tid & 7) * 8;

    for (int k0 = 0; k0 < 128; k0 += 32) {
        __syncthreads();
        {
            int gm = m0 + arow;
            uint2* dst = reinterpret_cast<uint2*>(sA) + arow * 10 + aseg * 4;
            if (gm < NN) {
                const float4* src = A4 + (size_t)gm * 32 + (k0 >> 2) + aseg * 4;
#pragma unroll
                for (int q = 0; q < 4; q++) dst[q] = st_h4(src[q]);
            } else {
                uint2 z = make_uint2(0u, 0u);
#pragma unroll
                for (int q = 0; q < 4; q++) dst[q] = z;
            }
        }
        {
            const float4* src = (const float4*)(g_wcat + (size_t)(k0 + brow) * 192 + n0 + bc8);
            uint2* dst = reinterpret_cast<uint2*>(sB) + brow * 18 + (tid & 7) * 2;
            dst[0] = st_h4(src[0]);
            dst[1] = st_h4(src[1]);
        }
        __syncthreads();
#pragma unroll
        for (int kk = 0; kk < 32; kk += 16) {
            wmma::fragment<wmma::matrix_a, 16, 16, 16, __half, wmma::row_major> a[2];
            wmma::fragment<wmma::matrix_b, 16, 16, 16, __half, wmma::row_major> b[2];
#pragma unroll
            for (int i = 0; i < 2; i++)
                wmma::load_matrix_sync(a[i], sA + (wm * 32 + i * 16) * 40 + kk, 40);
#pragma unroll
            for (int j = 0; j < 2; j++)
                wmma::load_matrix_sync(b[j], sB + kk * 72 + wn * 32 + j * 16, 72);
#pragma unroll
            for (int i = 0; i < 2; i++)
#pragma unroll
                for (int j = 0; j < 2; j++) wmma::mma_sync(c[i][j], a[i], b[j], c[i][j]);
        }
    }
#pragma unroll
    for (int i = 0; i < 2; i++)
#pragma unroll
        for (int j = 0; j < 2; j++)
            wmma::store_matrix_sync(sC + (wm * 32 + i * 16) * 64 + wn * 32 + j * 16,
                                    c[i][j], 64, wmma::mem_row_major);
    __syncthreads();
    {
        int row = tid >> 1, seg = tid & 1;
        int gm = m0 + row;
        if (gm < NN) {
            const float* src = sC + row * 64 + seg * 32;
            uint2* dst = g_P + (size_t)gm * 48 + (n0 >> 2) + seg * 8;
#pragma unroll
            for (int q = 0; q < 8; q++)
                dst[q] = st_h4(make_float4(src[q * 4], src[q * 4 + 1], src[q * 4 + 2], src[q * 4 + 3]));
        }
    }
}

// ---------------- gathers: 8 lanes/node, uint4 loads, 4-edge unroll (R13 form) ----------------
// gather 1: sum2 = sum dinv[s]*P2[s]; Rsc = dv*P1 - 2*dv^2*sum2
__global__ void k_gatherS() {
    int g = blockIdx.x * blockDim.x + threadIdx.x;
    int node = g >> 3;
    if (node >= NN) return;
    int lane = g & 7;
    int start = g_rowstart[node];
    int cnt = g_indeg[node];
    float4 sa = make_float4(0.f, 0.f, 0.f, 0.f);
    float4 sb = make_float4(0.f, 0.f, 0.f, 0.f);
    const int* cs = g_csri + start;
    int j = 0;
    for (; j + 4 <= cnt; j += 4) {
        int e[4];
        float ds[4];
        uint4 r[4];
#pragma unroll
        for (int u = 0; u < 4; u++) e[u] = cs[j + u];
#pragma unroll
        for (int u = 0; u < 4; u++) {
            ds[u] = g_dinv[e[u]];
            r[u] = *(const uint4*)(g_P + (size_t)e[u] * 48 + 32 + lane * 2);
        }
#pragma unroll
        for (int u = 0; u < 4; u++) acc8(sa, sb, r[u], ds[u]);
    }
    for (; j < cnt; j++) {
        int e0 = cs[j];
        uint4 r0 = *(const uint4*)(g_P + (size_t)e0 * 48 + 32 + lane * 2);
        acc8(sa, sb, r0, g_dinv[e0]);
    }
    float dv = g_dinv[node];
    float m = -2.f * dv * dv;
    float4 pa, pb;
    unp8(pa, pb, *(const uint4*)(g_P + (size_t)node * 48 + 16 + lane * 2));
    float4 oa = make_float4(dv * pa.x + m * sa.x, dv * pa.y + m * sa.y,
                            dv * pa.z + m * sa.z, dv * pa.w + m * sa.w);
    float4 ob = make_float4(dv * pb.x + m * sb.x, dv * pb.y + m * sb.y,
                            dv * pb.z + m * sb.z, dv * pb.w + m * sb.w);
    *(uint4*)(g_Rsc + (size_t)node * 16 + lane * 2) = pk8(oa, ob);
}

// gather 2: h1 = relu(P0 + b - dv*sum(Rsc[s])); store h1 and h1s = dv*h1
__global__ void k_combine64(const float* __restrict__ b1) {
    int g = blockIdx.x * blockDim.x + threadIdx.x;
    int node = g >> 3;
    if (node >= NN) return;
    int lane = g & 7;
    int start = g_rowstart[node];
    int cnt = g_indeg[node];
    float4 sa = make_float4(0.f, 0.f, 0.f, 0.f);
    float4 sb = make_float4(0.f, 0.f, 0.f, 0.f);
    const int* cs = g_csri + start;
    int j = 0;
    for (; j + 4 <= cnt; j += 4) {
        int e[4];
        uint4 r[4];
#pragma unroll
        for (int u = 0; u < 4; u++) e[u] = cs[j + u];
#pragma unroll
        for (int u = 0; u < 4; u++) r[u] = *(const uint4*)(g_Rsc + (size_t)e[u] * 16 + lane * 2);
#pragma unroll
        for (int u = 0; u < 4; u++) acc8(sa, sb, r[u], 1.f);
    }
    for (; j < cnt; j++) {
        acc8(sa, sb, *(const uint4*)(g_Rsc + (size_t)cs[j] * 16 + lane * 2), 1.f);
    }
    float dv = g_dinv[node];
    float4 pa, pb;
    unp8(pa, pb, *(const uint4*)(g_P + (size_t)node * 48 + lane * 2));
    float4 ba = *(const float4*)(b1 + lane * 8);
    float4 bb = *(const float4*)(b1 + lane * 8 + 4);
    float4 oa, ob;
    oa.x = fmaxf(pa.x + ba.x - dv * sa.x, 0.f);
    oa.y = fmaxf(pa.y + ba.y - dv * sa.y, 0.f);
    oa.z = fmaxf(pa.z + ba.z - dv * sa.z, 0.f);
    oa.w = fmaxf(pa.w + ba.w - dv * sa.w, 0.f);
    ob.x = fmaxf(pb.x + bb.x - dv * sb.x, 0.f);
    ob.y = fmaxf(pb.y + bb.y - dv * sb.y, 0.f);
    ob.z = fmaxf(pb.z + bb.z - dv * sb.z, 0.f);
    ob.w = fmaxf(pb.w + bb.w - dv * sb.w, 0.f);
    *(uint4*)(g_h1 + (size_t)node * 16 + lane * 2) = pk8(oa, ob);
    *(uint4*)(g_h1s + (size_t)node * 16 + lane * 2) = pk8(
        make_float4(dv * oa.x, dv * oa.y, dv * oa.z, dv * oa.w),
        make_float4(dv * ob.x, dv * ob.y, dv * ob.z, dv * ob.w));
}

// generic D=64 factorized gather (pre-scaled inputs):
// val = mul*dv*sum(in[s]) - (subsrc? subsrc[node]:0); out = val; outs = dv*val (optional)
__global__ void k_gather64(const uint2* __restrict__ in, uint2* __restrict__ out,
                           uint2* __restrict__ outs, const uint2* __restrict__ subsrc,
                           float mul) {
    int g = blockIdx.x * blockDim.x + threadIdx.x;
    int node = g >> 3;
    if (node >= NN) return;
    int lane = g & 7;
    int start = g_rowstart[node];
    int cnt = g_indeg[node];
    float4 sa = make_float4(0.f, 0.f, 0.f, 0.f);
    float4 sb = make_float4(0.f, 0.f, 0.f, 0.f);
    const int* cs = g_csri + start;
    int j = 0;
    for (; j + 4 <= cnt; j += 4) {
        int e[4];
        uint4 r[4];
#pragma unroll
        for (int u = 0; u < 4; u++) e[u] = cs[j + u];
#pragma unroll
        for (int u = 0; u < 4; u++) r[u] = *(const uint4*)(in + (size_t)e[u] * 16 + lane * 2);
#pragma unroll
        for (int u = 0; u < 4; u++) acc8(sa, sb, r[u], 1.f);
    }
    for (; j < cnt; j++) {
        acc8(sa, sb, *(const uint4*)(in + (size_t)cs[j] * 16 + lane * 2), 1.f);
    }
    float dv = g_dinv[node];
    float m = mul * dv;
    float4 va = make_float4(m * sa.x, m * sa.y, m * sa.z, m * sa.w);
    float4 vb = make_float4(m * sb.x, m * sb.y, m * sb.z, m * sb.w);
    if (subsrc) {
        float4 ta, tb;
        unp8(ta, tb, *(const uint4*)(subsrc + (size_t)node * 16 + lane * 2));
        va.x -= ta.x; va.y -= ta.y; va.z -= ta.z; va.w -= ta.w;
        vb.x -= tb.x; vb.y -= tb.y; vb.z -= tb.z; vb.w -= tb.w;
    }
    *(uint4*)(out + (size_t)node * 16 + lane * 2) = pk8(va, vb);
    if (outs)
        *(uint4*)(outs + (size_t)node * 16 + lane * 2) = pk8(
            make_float4(dv * va.x, dv * va.y, dv * va.z, dv * va.w),
            make_float4(dv * vb.x, dv * vb.y, dv * vb.z, dv * vb.w));
}

// ---------------- tensor-core GEMM 2: h2 = relu([h1|tb1|tb2] @ W2 + b2), fp16 out ----------------
__global__ void k_gemm3(const float* __restrict__ W, const float* __restrict__ bias) {
    __shared__ __align__(32) __half sA[128 * 40];
    __shared__ __align__(32) __half sB[32 * 72];
    __shared__ __align__(32) float  sC[128 * 64];
    const int tid = threadIdx.x;
    const int m0 = blockIdx.x * 128;
    const int wid = tid >> 5;
    const int wm = wid & 3, wn = wid >> 2;

    wmma::fragment<wmma::accumulator, 16, 16, 16, float> c[2][2];
#pragma unroll
    for (int i = 0; i < 2; i++)
#pragma unroll
        for (int j = 0; j < 2; j++) wmma::fill_fragment(c[i][j], 0.f);

    const int arow = tid >> 1, aseg = tid & 1;
    const int brow = tid >> 3, bc8 = (tid & 7) * 8;

    for (int k0 = 0; k0 < 192; k0 += 32) {
        const uint2* Asrc = (k0 < 64) ? g_h1 : (k0 < 128 ? g_tb1 : g_tb2);
        const int koff = (k0 & 63) >> 2;
        __syncthreads();
        {
            int gm = m0 + arow;
            uint2* dst = reinterpret_cast<uint2*>(sA) + arow * 10 + aseg * 4;
            if (gm < NN) {
                const uint2* src = Asrc + (size_t)gm * 16 + koff + aseg * 4;
#pragma unroll
                for (int q = 0; q < 4; q++) dst[q] = src[q];
            } else {
                uint2 z = make_uint2(0u, 0u);
#pragma unroll
                for (int q = 0; q < 4; q++) dst[q] = z;
            }
        }
        {
            const float4* src = (const float4*)(W + (size_t)(k0 + brow) * 64 + bc8);
            uint2* dst = reinterpret_cast<uint2*>(sB) + brow * 18 + (tid & 7) * 2;
            dst[0] = st_h4(src[0]);
            dst[1] = st_h4(src[1]);
        }
        __syncthreads();
#pragma unroll
        for (int kk = 0; kk < 32; kk += 16) {
            wmma::fragment<wmma::matrix_a, 16, 16, 16, __half, wmma::row_major> a[2];
            wmma::fragment<wmma::matrix_b, 16, 16, 16, __half, wmma::row_major> b[2];
#pragma unroll
            for (int i = 0; i < 2; i++)
                wmma::load_matrix_sync(a[i], sA + (wm * 32 + i * 16) * 40 + kk, 40);
#pragma unroll
            for (int j = 0; j < 2; j++)
                wmma::load_matrix_sync(b[j], sB + kk * 72 + wn * 32 + j * 16, 72);
#pragma unroll
            for (int i = 0; i < 2; i++)
#pragma unroll
                for (int j = 0; j < 2; j++) wmma::mma_sync(c[i][j], a[i], b[j], c[i][j]);
        }
    }
#pragma unroll
    for (int i = 0; i < 2; i++)
#pragma unroll
        for (int j = 0; j < 2; j++)
            wmma::store_matrix_sync(sC + (wm * 32 + i * 16) * 64 + wn * 32 + j * 16,
                                    c[i][j], 64, wmma::mem_row_major);
    __syncthreads();
    {
        int row = tid >> 1, seg = tid & 1;
        int gm = m0 + row;
        if (gm < NN) {
            const float* src = sC + row * 64 + seg * 32;
#pragma unroll
            for (int q = 0; q < 8; q++) {
                float4 bb = *(const float4*)(bias + seg * 32 + q * 4);
                float4 o;
                o.x = fmaxf(src[q * 4 + 0] + bb.x, 0.f);
                o.y = fmaxf(src[q * 4 + 1] + bb.y, 0.f);
                o.z = fmaxf(src[q * 4 + 2] + bb.z, 0.f);
                o.w = fmaxf(src[q * 4 + 3] + bb.w, 0.f);
                g_h2[(size_t)gm * 16 + seg * 8 + q] = st_h4(o);
            }
        }
    }
}

// ---------------- pooling + FC ----------------
__global__ void k_pool() {
    int col4 = threadIdx.x & 15;
    int sub = threadIdx.x >> 4;
    int n0 = blockIdx.x * 512 + sub * 32;
    float4 acc = make_float4(0.f, 0.f, 0.f, 0.f);
    int cur = -1;
    for (int k = 0; k < 32; k++) {
        int n = n0 + k;
        if (n >= NN) break;
        int gph = g_batch[n];
        if (gph != cur) {
            if (cur >= 0) {
                atomicAdd(&g_gsum[cur * 64 + col4 * 4 + 0], acc.x);
                atomicAdd(&g_gsum[cur * 64 + col4 * 4 + 1], acc.y);
                atomicAdd(&g_gsum[cur * 64 + col4 * 4 + 2], acc.z);
                atomicAdd(&g_gsum[cur * 64 + col4 * 4 + 3], acc.w);
            }
            cur = gph;
            acc = make_float4(0.f, 0.f, 0.f, 0.f);
        }
        float4 v = ld_h4(g_h2 + (size_t)n * 16 + col4);
        acc.x += v.x; acc.y += v.y; acc.z += v.z; acc.w += v.w;
    }
    if (cur >= 0) {
        atomicAdd(&g_gsum[cur * 64 + col4 * 4 + 0], acc.x);
        atomicAdd(&g_gsum[cur * 64 + col4 * 4 + 1], acc.y);
        atomicAdd(&g_gsum[cur * 64 + col4 * 4 + 2], acc.z);
        atomicAdd(&g_gsum[cur * 64 + col4 * 4 + 3], acc.w);
    }
}

__global__ void k_final(const float* __restrict__ Wfc, const float* __restrict__ bfc,
                        float* __restrict__ out) {
    int gph = threadIdx.x;
    if (gph < NG) {
        float c = fmaxf((float)(g_gend[gph] - g_gstart[gph]), 1.0f);
        float s = 0.f;
#pragma unroll
        for (int o = 0; o < 64; o++) s += g_gsum[gph * 64 + o] * Wfc[o];
        out[gph] = s / c + bfc[0];
    }
}

// ---------------- launch ----------------
extern "C" void kernel_launch(void* const* d_in, const int* in_sizes, int n_in,
                              void* d_out, int out_size) {
    const float *x = nullptr, *W1 = nullptr, *b1 = nullptr, *W2 = nullptr,
                *b2 = nullptr, *Wfc = nullptr, *bfc = nullptr;
    const void *ei = nullptr, *batch = nullptr;
    int idx64[3] = {-1, -1, -1};
    int n64 = 0, idxW2 = -1;
    for (int i = 0; i < n_in; i++) {
        int s = in_sizes[i];
        switch (s) {
            case 12800000: x = (const float*)d_in[i]; break;
            case 6400000:  ei = d_in[i]; break;
            case 100000:   batch = d_in[i]; break;
            case 24576:    W1 = (const float*)d_in[i]; break;
            case 12288:    W2 = (const float*)d_in[i]; idxW2 = i; break;
            case 1:        bfc = (const float*)d_in[i]; break;
            case 64:       if (n64 < 3) idx64[n64++] = i; break;
            default: break;
        }
    }
    if (n64 == 3) {
        if (idx64[0] < idxW2) {
            b1 = (const float*)d_in[idx64[0]];
            b2 = (const float*)d_in[idx64[1]];
            Wfc = (const float*)d_in[idx64[2]];
        } else {
            Wfc = (const float*)d_in[idx64[0]];
            b1 = (const float*)d_in[idx64[1]];
            b2 = (const float*)d_in[idx64[2]];
        }
    }
    float* out = (float*)d_out;

    uint2 *h1, *h1s, *tb1, *tb1s, *tb2;
    cudaGetSymbolAddress((void**)&h1, g_h1);
    cudaGetSymbolAddress((void**)&h1s, g_h1s);
    cudaGetSymbolAddress((void**)&tb1, g_tb1);
    cudaGetSymbolAddress((void**)&tb1s, g_tb1s);
    cudaGetSymbolAddress((void**)&tb2, g_tb2);

    static cudaStream_t s_side = nullptr;
    static cudaEvent_t s_fork = nullptr, s_join = nullptr;
    if (!s_side) {
        cudaStreamCreateWithFlags(&s_side, cudaStreamNonBlocking);
        cudaEventCreateWithFlags(&s_fork, cudaEventDisableTiming);
        cudaEventCreateWithFlags(&s_join, cudaEventDisableTiming);
    }

    const int TB = 256;
    const int g8 = (NN * 8 + TB - 1) / TB;

    // init (zero + dtype probe) FIRST, then fork
    k_init<<<(NN + TB - 1) / TB, TB>>>((const int*)ei, (const int*)batch);
    cudaEventRecord(s_fork, 0);
    cudaStreamWaitEvent(s_side, s_fork, 0);

    // side stream: weight prep + layer-1 GEMM + src-degree/dinv
    {
        dim3 gp((NN + 127) / 128, 3);
        k_wcat<<<(DIN * 192 + TB - 1) / TB, TB, 0, s_side>>>(W1);
        k_gemm_p<<<gp, TB, 0, s_side>>>((const float4*)x);
        k_degsrc<<<(NE / 2 + TB - 1) / TB, TB, 0, s_side>>>(ei);
        k_dinv<<<(NN + TB - 1) / TB, TB, 0, s_side>>>();
        cudaEventRecord(s_join, s_side);
    }

    // main stream: CSR build (in-degree only) + batch bookkeeping
    k_indeg<<<(NE / 2 + TB - 1) / TB, TB>>>(ei);
    k_batchb<<<(NN + TB - 1) / TB, TB>>>(batch);
    k_alloc<<<(NN + TB - 1) / TB, TB>>>();
    k_fill<<<(NE / 2 + TB - 1) / TB, TB>>>(ei);

    cudaStreamWaitEvent(0, s_join, 0);

    // layer 1: Rsc = dinv*(P1 + 2*Lhat(P2)); h1 = relu(P0 + b1 - dv*sum Rsc)
    k_gatherS<<<g8, TB>>>();
    k_combine64<<<g8, TB>>>(b1);

    // layer 2: tb1 = Lhat(h1); tb2 = 2*Lhat(tb1) - h1; h2 = relu([h1|tb1|tb2]@W2 + b2)
    k_gather64<<<g8, TB>>>(h1s, tb1, tb1s, nullptr, -1.0f);
    k_gather64<<<g8, TB>>>(tb1s, tb2, nullptr, h1, -2.0f);
    k_gemm3<<<(NN + 127) / 128, TB>>>(W2, b2);

    // mean pool per graph + FC
    k_pool<<<(NN + 511) / 512, TB>>>();
    k_final<<<1, TB>>>(Wfc, bfc, out);
}